// round 1
// baseline (speedup 1.0000x reference)
#include <cuda_runtime.h>
#include <cstdint>

// Problem shape (fixed by dataset): N=2,000,000 atoms, D=64, HID=32, H=3, G=50,000
#define D_DIM   64
#define HID_DIM 32
#define H_DIM   3

#define MAX_N 2000000
#define MAX_G 50000

// Scratch (device globals: no allocation allowed in kernel_launch)
__device__ float g_scores[(size_t)MAX_N * H_DIM];   // 24 MB
__device__ int   g_segstart[MAX_G + 1];

// ---------------------------------------------------------------------------
// Kernel 1: per-atom MLP scores  s = silu(x@w1 + b1) @ w2 + b2
// One thread per atom. w1 broadcast from SMEM (LDS broadcast pairs with FFMA).
// ---------------------------------------------------------------------------
__global__ __launch_bounds__(128) void k_scores(
    const float* __restrict__ X,
    const float* __restrict__ w1, const float* __restrict__ b1,
    const float* __restrict__ w2, const float* __restrict__ b2,
    int N)
{
    __shared__ float w1s[D_DIM * HID_DIM];   // 8 KB, [k][j] layout
    __shared__ float b1s[HID_DIM];
    __shared__ float w2s[HID_DIM * H_DIM];
    __shared__ float b2s[H_DIM];

    for (int i = threadIdx.x; i < D_DIM * HID_DIM; i += 128) w1s[i] = w1[i];
    if (threadIdx.x < HID_DIM)          b1s[threadIdx.x] = b1[threadIdx.x];
    if (threadIdx.x < HID_DIM * H_DIM)  w2s[threadIdx.x] = w2[threadIdx.x];
    if (threadIdx.x < H_DIM)            b2s[threadIdx.x] = b2[threadIdx.x];
    __syncthreads();

    int i = blockIdx.x * 128 + threadIdx.x;
    if (i >= N) return;

    const float4* xp = reinterpret_cast<const float4*>(X + (size_t)i * D_DIM);

    float h[HID_DIM];
#pragma unroll
    for (int j = 0; j < HID_DIM; ++j) h[j] = b1s[j];

#pragma unroll 2
    for (int k4 = 0; k4 < D_DIM / 4; ++k4) {
        float4 xv = xp[k4];
        const float* wr = &w1s[k4 * 4 * HID_DIM];
#pragma unroll
        for (int j = 0; j < HID_DIM; ++j) h[j] = fmaf(xv.x, wr[j], h[j]);
#pragma unroll
        for (int j = 0; j < HID_DIM; ++j) h[j] = fmaf(xv.y, wr[HID_DIM + j], h[j]);
#pragma unroll
        for (int j = 0; j < HID_DIM; ++j) h[j] = fmaf(xv.z, wr[2 * HID_DIM + j], h[j]);
#pragma unroll
        for (int j = 0; j < HID_DIM; ++j) h[j] = fmaf(xv.w, wr[3 * HID_DIM + j], h[j]);
    }

    float s0 = b2s[0], s1 = b2s[1], s2 = b2s[2];
#pragma unroll
    for (int j = 0; j < HID_DIM; ++j) {
        float a = h[j];
        float act = a / (1.0f + __expf(-a));   // SiLU
        s0 = fmaf(act, w2s[j * H_DIM + 0], s0);
        s1 = fmaf(act, w2s[j * H_DIM + 1], s1);
        s2 = fmaf(act, w2s[j * H_DIM + 2], s2);
    }

    size_t o = (size_t)i * H_DIM;
    g_scores[o + 0] = s0;
    g_scores[o + 1] = s1;
    g_scores[o + 2] = s2;
}

// ---------------------------------------------------------------------------
// Kernel 2: segment boundaries from sorted owner array.
// g_segstart[g] = first index i with owner[i] >= g ; g_segstart[G] = N
// ---------------------------------------------------------------------------
__global__ void k_bounds(const int* __restrict__ owner, int N, int G)
{
    int i = blockIdx.x * blockDim.x + threadIdx.x;
    if (i >= N) return;
    int o = owner[i];
    if (i == 0) {
        for (int g = 0; g <= o; ++g) g_segstart[g] = 0;
    } else {
        int po = owner[i - 1];
        for (int g = po + 1; g <= o; ++g) g_segstart[g] = i;
    }
    if (i == N - 1) {
        for (int g = o + 1; g <= G; ++g) g_segstart[g] = N;
    }
}

// ---------------------------------------------------------------------------
// Kernel 3: one block per segment. Segment softmax (max, expsum) over cached
// scores, then weighted pooling out[g, d*3+h] = sum_n X[n,d] * attn[n,h].
// 128 threads: 2 groups of 64; group handles alternating atoms, d = t&63.
// ---------------------------------------------------------------------------
__global__ __launch_bounds__(128) void k_pool(
    const float* __restrict__ X, float* __restrict__ out)
{
    const int g  = blockIdx.x;
    const int t  = threadIdx.x;
    const int s0 = g_segstart[g];
    const int s1 = g_segstart[g + 1];

    if (s1 <= s0) {   // empty segment -> zeros (out is poisoned)
        if (t < D_DIM) {
            size_t o = (size_t)g * (D_DIM * H_DIM) + t * H_DIM;
            out[o + 0] = 0.f; out[o + 1] = 0.f; out[o + 2] = 0.f;
        }
        return;
    }

    const int lane = t & 31, warp = t >> 5;
    __shared__ float wred[4][H_DIM];
    __shared__ float mhd[H_DIM];
    __shared__ float rden[H_DIM];
    __shared__ float sp[64 * H_DIM];
    __shared__ float accb[D_DIM * H_DIM];

    // ---- per-head max ----
    float m0 = -3.4e38f, m1 = -3.4e38f, m2 = -3.4e38f;
    for (int n = s0 + t; n < s1; n += 128) {
        size_t o = (size_t)n * H_DIM;
        m0 = fmaxf(m0, g_scores[o + 0]);
        m1 = fmaxf(m1, g_scores[o + 1]);
        m2 = fmaxf(m2, g_scores[o + 2]);
    }
#pragma unroll
    for (int off = 16; off; off >>= 1) {
        m0 = fmaxf(m0, __shfl_xor_sync(0xffffffffu, m0, off));
        m1 = fmaxf(m1, __shfl_xor_sync(0xffffffffu, m1, off));
        m2 = fmaxf(m2, __shfl_xor_sync(0xffffffffu, m2, off));
    }
    if (lane == 0) { wred[warp][0] = m0; wred[warp][1] = m1; wred[warp][2] = m2; }
    __syncthreads();
    if (t == 0) {
#pragma unroll
        for (int c = 0; c < H_DIM; ++c)
            mhd[c] = fmaxf(fmaxf(wred[0][c], wred[1][c]), fmaxf(wred[2][c], wred[3][c]));
    }
    __syncthreads();
    m0 = mhd[0]; m1 = mhd[1]; m2 = mhd[2];

    // ---- per-head exp sum ----
    float e0 = 0.f, e1 = 0.f, e2 = 0.f;
    for (int n = s0 + t; n < s1; n += 128) {
        size_t o = (size_t)n * H_DIM;
        e0 += __expf(g_scores[o + 0] - m0);
        e1 += __expf(g_scores[o + 1] - m1);
        e2 += __expf(g_scores[o + 2] - m2);
    }
#pragma unroll
    for (int off = 16; off; off >>= 1) {
        e0 += __shfl_xor_sync(0xffffffffu, e0, off);
        e1 += __shfl_xor_sync(0xffffffffu, e1, off);
        e2 += __shfl_xor_sync(0xffffffffu, e2, off);
    }
    if (lane == 0) { wred[warp][0] = e0; wred[warp][1] = e1; wred[warp][2] = e2; }
    __syncthreads();
    if (t == 0) {
#pragma unroll
        for (int c = 0; c < H_DIM; ++c)
            rden[c] = 1.0f / (wred[0][c] + wred[1][c] + wred[2][c] + wred[3][c]);
    }
    __syncthreads();
    const float r0 = rden[0], r1 = rden[1], r2 = rden[2];

    // ---- weighted pooling over X rows, in tiles of 64 atoms ----
    const int grp = t >> 6;      // 0 or 1
    const int d   = t & 63;
    float a0 = 0.f, a1 = 0.f, a2 = 0.f;

    for (int base = s0; base < s1; base += 64) {
        const int cnt = min(64, s1 - base);
        __syncthreads();
        if (t < cnt) {
            size_t o = (size_t)(base + t) * H_DIM;
            sp[t * 3 + 0] = __expf(g_scores[o + 0] - m0) * r0;
            sp[t * 3 + 1] = __expf(g_scores[o + 1] - m1) * r1;
            sp[t * 3 + 2] = __expf(g_scores[o + 2] - m2) * r2;
        }
        __syncthreads();
        for (int a = grp; a < cnt; a += 2) {
            float xv = X[(size_t)(base + a) * D_DIM + d];
            a0 = fmaf(xv, sp[a * 3 + 0], a0);
            a1 = fmaf(xv, sp[a * 3 + 1], a1);
            a2 = fmaf(xv, sp[a * 3 + 2], a2);
        }
    }

    // combine the two atom-groups
    if (grp == 1) { accb[d * 3 + 0] = a0; accb[d * 3 + 1] = a1; accb[d * 3 + 2] = a2; }
    __syncthreads();
    if (grp == 0) {
        size_t o = (size_t)g * (D_DIM * H_DIM) + d * H_DIM;
        out[o + 0] = a0 + accb[d * 3 + 0];
        out[o + 1] = a1 + accb[d * 3 + 1];
        out[o + 2] = a2 + accb[d * 3 + 2];
    }
}

// ---------------------------------------------------------------------------
extern "C" void kernel_launch(void* const* d_in, const int* in_sizes, int n_in,
                              void* d_out, int out_size)
{
    const float* X     = (const float*)d_in[0];
    const float* w1    = (const float*)d_in[1];
    const float* b1    = (const float*)d_in[2];
    const float* w2    = (const float*)d_in[3];
    const float* b2    = (const float*)d_in[4];
    const int*   owner = (const int*)  d_in[5];

    const int N = in_sizes[5];
    const int G = out_size / (D_DIM * H_DIM);

    k_scores<<<(N + 127) / 128, 128>>>(X, w1, b1, w2, b2, N);
    k_bounds<<<(N + 255) / 256, 256>>>(owner, N, G);
    k_pool<<<G, 128>>>(X, (float*)d_out);
}

// round 2
// speedup vs baseline: 1.3526x; 1.3526x over previous
#include <cuda_runtime.h>
#include <cstdint>

// Problem shape (fixed by dataset): N=2,000,000 atoms, D=64, HID=32, H=3, G=50,000
#define D_DIM   64
#define HID_DIM 32
#define H_DIM   3

#define MAX_N 2000000
#define MAX_G 50000
#define SEG_CAP 128   // fast-path cap on atoms per segment (avg ~40, max ~75)

typedef unsigned long long ull;

// Scratch (device globals: no allocation allowed in kernel_launch)
__device__ float g_scores[(size_t)MAX_N * H_DIM];   // 24 MB
__device__ int   g_segstart[MAX_G + 1];

// ---------------- packed fp32x2 helpers (sm_103a FFMA2) ----------------
__device__ __forceinline__ ull pack2(float v) {
    ull r; asm("mov.b64 %0, {%1, %1};" : "=l"(r) : "f"(v)); return r;
}
__device__ __forceinline__ ull fma2(ull a, ull b, ull c) {
    ull d; asm("fma.rn.f32x2 %0, %1, %2, %3;" : "=l"(d) : "l"(a), "l"(b), "l"(c)); return d;
}
__device__ __forceinline__ void unpack2(ull v, float& lo, float& hi) {
    asm("mov.b64 {%0, %1}, %2;" : "=f"(lo), "=f"(hi) : "l"(v));
}

// ---------------------------------------------------------------------------
// Kernel 1: per-atom MLP scores  s = silu(x@w1 + b1) @ w2 + b2
// One thread per atom; hidden vector held as 16 packed f32x2 accumulators.
// ---------------------------------------------------------------------------
__global__ __launch_bounds__(128) void k_scores(
    const float* __restrict__ X,
    const float* __restrict__ w1, const float* __restrict__ b1,
    const float* __restrict__ w2, const float* __restrict__ b2,
    int N)
{
    __shared__ __align__(16) float w1s[D_DIM * HID_DIM];   // [k][j], j contiguous
    __shared__ __align__(16) float b1s[HID_DIM];
    __shared__ float w2s[HID_DIM * H_DIM];
    __shared__ float b2s[H_DIM];

    for (int i = threadIdx.x; i < D_DIM * HID_DIM; i += 128) w1s[i] = w1[i];
    if (threadIdx.x < HID_DIM)          b1s[threadIdx.x] = b1[threadIdx.x];
    if (threadIdx.x < HID_DIM * H_DIM)  w2s[threadIdx.x] = w2[threadIdx.x];
    if (threadIdx.x < H_DIM)            b2s[threadIdx.x] = b2[threadIdx.x];
    __syncthreads();

    int i = blockIdx.x * 128 + threadIdx.x;
    if (i >= N) return;

    const float4* xp  = reinterpret_cast<const float4*>(X + (size_t)i * D_DIM);
    const ull*    w1u = reinterpret_cast<const ull*>(w1s);   // [k][j-pair], 16 pairs/row
    const ull*    b1u = reinterpret_cast<const ull*>(b1s);

    ull h2[HID_DIM / 2];
#pragma unroll
    for (int p = 0; p < HID_DIM / 2; ++p) h2[p] = b1u[p];

#pragma unroll 4
    for (int k4 = 0; k4 < D_DIM / 4; ++k4) {
        float4 xv = xp[k4];
        {
            ull xx = pack2(xv.x);
            const ull* wr = w1u + (k4 * 4 + 0) * (HID_DIM / 2);
#pragma unroll
            for (int p = 0; p < HID_DIM / 2; ++p) h2[p] = fma2(xx, wr[p], h2[p]);
        }
        {
            ull xx = pack2(xv.y);
            const ull* wr = w1u + (k4 * 4 + 1) * (HID_DIM / 2);
#pragma unroll
            for (int p = 0; p < HID_DIM / 2; ++p) h2[p] = fma2(xx, wr[p], h2[p]);
        }
        {
            ull xx = pack2(xv.z);
            const ull* wr = w1u + (k4 * 4 + 2) * (HID_DIM / 2);
#pragma unroll
            for (int p = 0; p < HID_DIM / 2; ++p) h2[p] = fma2(xx, wr[p], h2[p]);
        }
        {
            ull xx = pack2(xv.w);
            const ull* wr = w1u + (k4 * 4 + 3) * (HID_DIM / 2);
#pragma unroll
            for (int p = 0; p < HID_DIM / 2; ++p) h2[p] = fma2(xx, wr[p], h2[p]);
        }
    }

    float s0 = b2s[0], s1 = b2s[1], s2 = b2s[2];
#pragma unroll
    for (int p = 0; p < HID_DIM / 2; ++p) {
        float a, b;
        unpack2(h2[p], a, b);
        float acta = __fdividef(a, 1.0f + __expf(-a));   // SiLU
        float actb = __fdividef(b, 1.0f + __expf(-b));
        int j0 = 2 * p, j1 = 2 * p + 1;
        s0 = fmaf(acta, w2s[j0 * H_DIM + 0], s0);
        s1 = fmaf(acta, w2s[j0 * H_DIM + 1], s1);
        s2 = fmaf(acta, w2s[j0 * H_DIM + 2], s2);
        s0 = fmaf(actb, w2s[j1 * H_DIM + 0], s0);
        s1 = fmaf(actb, w2s[j1 * H_DIM + 1], s1);
        s2 = fmaf(actb, w2s[j1 * H_DIM + 2], s2);
    }

    size_t o = (size_t)i * H_DIM;
    g_scores[o + 0] = s0;
    g_scores[o + 1] = s1;
    g_scores[o + 2] = s2;
}

// ---------------------------------------------------------------------------
// Kernel 2: segment boundaries from sorted owner array.
// ---------------------------------------------------------------------------
__global__ void k_bounds(const int* __restrict__ owner, int N, int G)
{
    int i = blockIdx.x * blockDim.x + threadIdx.x;
    if (i >= N) return;
    int o = owner[i];
    if (i == 0) {
        for (int g = 0; g <= o; ++g) g_segstart[g] = 0;
    } else {
        int po = owner[i - 1];
        for (int g = po + 1; g <= o; ++g) g_segstart[g] = i;
    }
    if (i == N - 1) {
        for (int g = o + 1; g <= G; ++g) g_segstart[g] = N;
    }
}

// ---------------------------------------------------------------------------
// Kernel 3: one WARP per segment. Softmax in registers + warp shuffles,
// attn weights staged to per-warp smem, pooling with f32x2 FMA.
// Each lane owns d = {2*lane, 2*lane+1} (float2 of the X row).
// ---------------------------------------------------------------------------
__global__ __launch_bounds__(128) void k_pool(
    const float* __restrict__ X, float* __restrict__ out, int G)
{
    __shared__ float sw[4][SEG_CAP * H_DIM];

    const int warp = threadIdx.x >> 5;
    const int lane = threadIdx.x & 31;
    const int g    = blockIdx.x * 4 + warp;
    if (g >= G) return;

    const int s0  = g_segstart[g];
    const int s1  = g_segstart[g + 1];
    const int cnt = s1 - s0;

    float* outg = out + (size_t)g * (D_DIM * H_DIM);
    if (cnt <= 0) {   // empty segment -> zeros
        for (int i = lane; i < D_DIM * H_DIM; i += 32) outg[i] = 0.f;
        return;
    }

    float* swp = sw[warp];
    const float2* X2 = reinterpret_cast<const float2*>(X);

    float m0 = -3.4e38f, m1 = -3.4e38f, m2 = -3.4e38f;
    float r0, r1, r2;
    ull acc0 = 0ull, acc1 = 0ull, acc2 = 0ull;

    if (cnt <= SEG_CAP) {
        // ---- fast path: scores live in registers ----
        float sc[4][3];
#pragma unroll
        for (int q = 0; q < 4; ++q) {
            int a = lane + 32 * q;
            if (a < cnt) {
                size_t o = (size_t)(s0 + a) * H_DIM;
                sc[q][0] = g_scores[o + 0];
                sc[q][1] = g_scores[o + 1];
                sc[q][2] = g_scores[o + 2];
                m0 = fmaxf(m0, sc[q][0]);
                m1 = fmaxf(m1, sc[q][1]);
                m2 = fmaxf(m2, sc[q][2]);
            }
        }
#pragma unroll
        for (int off = 16; off; off >>= 1) {
            m0 = fmaxf(m0, __shfl_xor_sync(0xffffffffu, m0, off));
            m1 = fmaxf(m1, __shfl_xor_sync(0xffffffffu, m1, off));
            m2 = fmaxf(m2, __shfl_xor_sync(0xffffffffu, m2, off));
        }
        float e0 = 0.f, e1 = 0.f, e2 = 0.f;
#pragma unroll
        for (int q = 0; q < 4; ++q) {
            int a = lane + 32 * q;
            if (a < cnt) {
                sc[q][0] = __expf(sc[q][0] - m0); e0 += sc[q][0];
                sc[q][1] = __expf(sc[q][1] - m1); e1 += sc[q][1];
                sc[q][2] = __expf(sc[q][2] - m2); e2 += sc[q][2];
            }
        }
#pragma unroll
        for (int off = 16; off; off >>= 1) {
            e0 += __shfl_xor_sync(0xffffffffu, e0, off);
            e1 += __shfl_xor_sync(0xffffffffu, e1, off);
            e2 += __shfl_xor_sync(0xffffffffu, e2, off);
        }
        r0 = 1.0f / e0; r1 = 1.0f / e1; r2 = 1.0f / e2;
#pragma unroll
        for (int q = 0; q < 4; ++q) {
            int a = lane + 32 * q;
            if (a < cnt) {
                swp[a * 3 + 0] = sc[q][0] * r0;
                swp[a * 3 + 1] = sc[q][1] * r1;
                swp[a * 3 + 2] = sc[q][2] * r2;
            }
        }
        __syncwarp();

#pragma unroll 4
        for (int a = 0; a < cnt; ++a) {
            float2 xv = X2[(size_t)(s0 + a) * (D_DIM / 2) + lane];
            ull xx = *reinterpret_cast<ull*>(&xv);
            acc0 = fma2(xx, pack2(swp[a * 3 + 0]), acc0);
            acc1 = fma2(xx, pack2(swp[a * 3 + 1]), acc1);
            acc2 = fma2(xx, pack2(swp[a * 3 + 2]), acc2);
        }
    } else {
        // ---- generic path: arbitrary segment length ----
        for (int n = s0 + lane; n < s1; n += 32) {
            size_t o = (size_t)n * H_DIM;
            m0 = fmaxf(m0, g_scores[o + 0]);
            m1 = fmaxf(m1, g_scores[o + 1]);
            m2 = fmaxf(m2, g_scores[o + 2]);
        }
#pragma unroll
        for (int off = 16; off; off >>= 1) {
            m0 = fmaxf(m0, __shfl_xor_sync(0xffffffffu, m0, off));
            m1 = fmaxf(m1, __shfl_xor_sync(0xffffffffu, m1, off));
            m2 = fmaxf(m2, __shfl_xor_sync(0xffffffffu, m2, off));
        }
        float e0 = 0.f, e1 = 0.f, e2 = 0.f;
        for (int n = s0 + lane; n < s1; n += 32) {
            size_t o = (size_t)n * H_DIM;
            e0 += __expf(g_scores[o + 0] - m0);
            e1 += __expf(g_scores[o + 1] - m1);
            e2 += __expf(g_scores[o + 2] - m2);
        }
#pragma unroll
        for (int off = 16; off; off >>= 1) {
            e0 += __shfl_xor_sync(0xffffffffu, e0, off);
            e1 += __shfl_xor_sync(0xffffffffu, e1, off);
            e2 += __shfl_xor_sync(0xffffffffu, e2, off);
        }
        r0 = 1.0f / e0; r1 = 1.0f / e1; r2 = 1.0f / e2;

        for (int base = 0; base < cnt; base += SEG_CAP) {
            int c = min(SEG_CAP, cnt - base);
#pragma unroll
            for (int q = 0; q < 4; ++q) {
                int a = lane + 32 * q;
                if (a < c) {
                    size_t o = (size_t)(s0 + base + a) * H_DIM;
                    swp[a * 3 + 0] = __expf(g_scores[o + 0] - m0) * r0;
                    swp[a * 3 + 1] = __expf(g_scores[o + 1] - m1) * r1;
                    swp[a * 3 + 2] = __expf(g_scores[o + 2] - m2) * r2;
                }
            }
            __syncwarp();
#pragma unroll 4
            for (int a = 0; a < c; ++a) {
                float2 xv = X2[(size_t)(s0 + base + a) * (D_DIM / 2) + lane];
                ull xx = *reinterpret_cast<ull*>(&xv);
                acc0 = fma2(xx, pack2(swp[a * 3 + 0]), acc0);
                acc1 = fma2(xx, pack2(swp[a * 3 + 1]), acc1);
                acc2 = fma2(xx, pack2(swp[a * 3 + 2]), acc2);
            }
            __syncwarp();
        }
    }

    // ---- write out: lane owns d = 2*lane, 2*lane+1 ; out layout [g][d][h] ----
    float v00, v01, v10, v11, v20, v21;
    unpack2(acc0, v00, v01);
    unpack2(acc1, v10, v11);
    unpack2(acc2, v20, v21);
    float* po = outg + lane * 6;
    po[0] = v00; po[1] = v10; po[2] = v20;
    po[3] = v01; po[4] = v11; po[5] = v21;
}

// ---------------------------------------------------------------------------
extern "C" void kernel_launch(void* const* d_in, const int* in_sizes, int n_in,
                              void* d_out, int out_size)
{
    const float* X     = (const float*)d_in[0];
    const float* w1    = (const float*)d_in[1];
    const float* b1    = (const float*)d_in[2];
    const float* w2    = (const float*)d_in[3];
    const float* b2    = (const float*)d_in[4];
    const int*   owner = (const int*)  d_in[5];

    const int N = in_sizes[5];
    const int G = out_size / (D_DIM * H_DIM);

    k_scores<<<(N + 127) / 128, 128>>>(X, w1, b1, w2, b2, N);
    k_bounds<<<(N + 255) / 256, 256>>>(owner, N, G);
    k_pool<<<(G + 3) / 4, 128>>>(X, (float*)d_out, G);
}

// round 3
// speedup vs baseline: 1.5407x; 1.1391x over previous
#include <cuda_runtime.h>
#include <cstdint>

// Problem shape (fixed by dataset): N=2,000,000 atoms, D=64, HID=32, H=3, G=50,000
#define D_DIM   64
#define HID_DIM 32
#define H_DIM   3

#define MAX_N 2000000
#define MAX_G 50000
#define SEG_CAP 128

typedef unsigned long long ull;

// Scratch (device globals: no allocation allowed in kernel_launch)
__device__ float g_scores[(size_t)MAX_N * H_DIM];   // 24 MB
__device__ int   g_segstart[MAX_G + 1];

// ---------------- packed fp32x2 helpers (sm_103a FFMA2) ----------------
__device__ __forceinline__ ull pack2(float v) {
    ull r; asm("mov.b64 %0, {%1, %1};" : "=l"(r) : "f"(v)); return r;
}
__device__ __forceinline__ ull fma2(ull a, ull b, ull c) {
    ull d; asm("fma.rn.f32x2 %0, %1, %2, %3;" : "=l"(d) : "l"(a), "l"(b), "l"(c)); return d;
}
__device__ __forceinline__ void unpack2(ull v, float& lo, float& hi) {
    asm("mov.b64 {%0, %1}, %2;" : "=f"(lo), "=f"(hi) : "l"(v));
}

// ---------------------------------------------------------------------------
// Kernel 1: per-atom MLP scores  s = silu(x@w1 + b1) @ w2 + b2
// TWO atoms per thread (amortizes weight LDS 2x), weights read as LDS.128.
// ---------------------------------------------------------------------------
__global__ __launch_bounds__(256) void k_scores(
    const float* __restrict__ X,
    const float* __restrict__ w1, const float* __restrict__ b1,
    const float* __restrict__ w2, const float* __restrict__ b2,
    int N)
{
    __shared__ __align__(16) float w1s[D_DIM * HID_DIM];   // [k][j], j contiguous
    __shared__ __align__(16) float b1s[HID_DIM];
    __shared__ float w2s[HID_DIM * H_DIM];
    __shared__ float b2s[H_DIM];

    for (int i = threadIdx.x; i < D_DIM * HID_DIM; i += 256) w1s[i] = w1[i];
    if (threadIdx.x < HID_DIM)          b1s[threadIdx.x] = b1[threadIdx.x];
    if (threadIdx.x < HID_DIM * H_DIM)  w2s[threadIdx.x] = w2[threadIdx.x];
    if (threadIdx.x < H_DIM)            b2s[threadIdx.x] = b2[threadIdx.x];
    __syncthreads();

    const int i0 = blockIdx.x * 512 + threadIdx.x;
    const int i1 = i0 + 256;
    if (i0 >= N) return;
    const bool has1 = (i1 < N);
    const int  i1c  = has1 ? i1 : i0;

    const float4* xpa = reinterpret_cast<const float4*>(X + (size_t)i0  * D_DIM);
    const float4* xpb = reinterpret_cast<const float4*>(X + (size_t)i1c * D_DIM);
    const ull*    b1u = reinterpret_cast<const ull*>(b1s);

    ull ha[HID_DIM / 2], hb[HID_DIM / 2];
#pragma unroll
    for (int p = 0; p < HID_DIM / 2; ++p) { ull b = b1u[p]; ha[p] = b; hb[p] = b; }

#define K_STEP(CA, CB, KROW)                                                   \
    {                                                                          \
        ull xxa = pack2(CA), xxb = pack2(CB);                                  \
        const ulonglong2* wr =                                                 \
            reinterpret_cast<const ulonglong2*>(w1s + (KROW) * HID_DIM);       \
        _Pragma("unroll")                                                      \
        for (int p2 = 0; p2 < HID_DIM / 4; ++p2) {                             \
            ulonglong2 w = wr[p2];                                             \
            ha[2 * p2]     = fma2(xxa, w.x, ha[2 * p2]);                       \
            ha[2 * p2 + 1] = fma2(xxa, w.y, ha[2 * p2 + 1]);                   \
            hb[2 * p2]     = fma2(xxb, w.x, hb[2 * p2]);                       \
            hb[2 * p2 + 1] = fma2(xxb, w.y, hb[2 * p2 + 1]);                   \
        }                                                                      \
    }

#pragma unroll 2
    for (int k4 = 0; k4 < D_DIM / 4; ++k4) {
        float4 xa = xpa[k4];
        float4 xb = xpb[k4];
        K_STEP(xa.x, xb.x, k4 * 4 + 0)
        K_STEP(xa.y, xb.y, k4 * 4 + 1)
        K_STEP(xa.z, xb.z, k4 * 4 + 2)
        K_STEP(xa.w, xb.w, k4 * 4 + 3)
    }
#undef K_STEP

    // ---- epilogue: SiLU + second linear, per atom ----
    {
        float s0 = b2s[0], s1 = b2s[1], s2 = b2s[2];
#pragma unroll
        for (int p = 0; p < HID_DIM / 2; ++p) {
            float a, b; unpack2(ha[p], a, b);
            float acta = __fdividef(a, 1.0f + __expf(-a));
            float actb = __fdividef(b, 1.0f + __expf(-b));
            int j0 = 2 * p, j1 = 2 * p + 1;
            s0 = fmaf(acta, w2s[j0 * H_DIM + 0], s0);
            s1 = fmaf(acta, w2s[j0 * H_DIM + 1], s1);
            s2 = fmaf(acta, w2s[j0 * H_DIM + 2], s2);
            s0 = fmaf(actb, w2s[j1 * H_DIM + 0], s0);
            s1 = fmaf(actb, w2s[j1 * H_DIM + 1], s1);
            s2 = fmaf(actb, w2s[j1 * H_DIM + 2], s2);
        }
        size_t o = (size_t)i0 * H_DIM;
        g_scores[o + 0] = s0; g_scores[o + 1] = s1; g_scores[o + 2] = s2;
    }
    if (has1) {
        float s0 = b2s[0], s1 = b2s[1], s2 = b2s[2];
#pragma unroll
        for (int p = 0; p < HID_DIM / 2; ++p) {
            float a, b; unpack2(hb[p], a, b);
            float acta = __fdividef(a, 1.0f + __expf(-a));
            float actb = __fdividef(b, 1.0f + __expf(-b));
            int j0 = 2 * p, j1 = 2 * p + 1;
            s0 = fmaf(acta, w2s[j0 * H_DIM + 0], s0);
            s1 = fmaf(acta, w2s[j0 * H_DIM + 1], s1);
            s2 = fmaf(acta, w2s[j0 * H_DIM + 2], s2);
            s0 = fmaf(actb, w2s[j1 * H_DIM + 0], s0);
            s1 = fmaf(actb, w2s[j1 * H_DIM + 1], s1);
            s2 = fmaf(actb, w2s[j1 * H_DIM + 2], s2);
        }
        size_t o = (size_t)i1 * H_DIM;
        g_scores[o + 0] = s0; g_scores[o + 1] = s1; g_scores[o + 2] = s2;
    }
}

// ---------------------------------------------------------------------------
// Kernel 2: segment boundaries from sorted owner array.
// ---------------------------------------------------------------------------
__global__ void k_bounds(const int* __restrict__ owner, int N, int G)
{
    int i = blockIdx.x * blockDim.x + threadIdx.x;
    if (i >= N) return;
    int o = owner[i];
    if (i == 0) {
        for (int g = 0; g <= o; ++g) g_segstart[g] = 0;
    } else {
        int po = owner[i - 1];
        for (int g = po + 1; g <= o; ++g) g_segstart[g] = i;
    }
    if (i == N - 1) {
        for (int g = o + 1; g <= G; ++g) g_segstart[g] = N;
    }
}

// ---------------------------------------------------------------------------
// Kernel 3: one WARP per segment (unchanged from R2 — performed as predicted).
// ---------------------------------------------------------------------------
__global__ __launch_bounds__(128) void k_pool(
    const float* __restrict__ X, float* __restrict__ out, int G)
{
    __shared__ float sw[4][SEG_CAP * H_DIM];

    const int warp = threadIdx.x >> 5;
    const int lane = threadIdx.x & 31;
    const int g    = blockIdx.x * 4 + warp;
    if (g >= G) return;

    const int s0  = g_segstart[g];
    const int s1  = g_segstart[g + 1];
    const int cnt = s1 - s0;

    float* outg = out + (size_t)g * (D_DIM * H_DIM);
    if (cnt <= 0) {
        for (int i = lane; i < D_DIM * H_DIM; i += 32) outg[i] = 0.f;
        return;
    }

    float* swp = sw[warp];
    const float2* X2 = reinterpret_cast<const float2*>(X);

    float m0 = -3.4e38f, m1 = -3.4e38f, m2 = -3.4e38f;
    float r0, r1, r2;
    ull acc0 = 0ull, acc1 = 0ull, acc2 = 0ull;

    if (cnt <= SEG_CAP) {
        float sc[4][3];
#pragma unroll
        for (int q = 0; q < 4; ++q) {
            int a = lane + 32 * q;
            if (a < cnt) {
                size_t o = (size_t)(s0 + a) * H_DIM;
                sc[q][0] = g_scores[o + 0];
                sc[q][1] = g_scores[o + 1];
                sc[q][2] = g_scores[o + 2];
                m0 = fmaxf(m0, sc[q][0]);
                m1 = fmaxf(m1, sc[q][1]);
                m2 = fmaxf(m2, sc[q][2]);
            }
        }
#pragma unroll
        for (int off = 16; off; off >>= 1) {
            m0 = fmaxf(m0, __shfl_xor_sync(0xffffffffu, m0, off));
            m1 = fmaxf(m1, __shfl_xor_sync(0xffffffffu, m1, off));
            m2 = fmaxf(m2, __shfl_xor_sync(0xffffffffu, m2, off));
        }
        float e0 = 0.f, e1 = 0.f, e2 = 0.f;
#pragma unroll
        for (int q = 0; q < 4; ++q) {
            int a = lane + 32 * q;
            if (a < cnt) {
                sc[q][0] = __expf(sc[q][0] - m0); e0 += sc[q][0];
                sc[q][1] = __expf(sc[q][1] - m1); e1 += sc[q][1];
                sc[q][2] = __expf(sc[q][2] - m2); e2 += sc[q][2];
            }
        }
#pragma unroll
        for (int off = 16; off; off >>= 1) {
            e0 += __shfl_xor_sync(0xffffffffu, e0, off);
            e1 += __shfl_xor_sync(0xffffffffu, e1, off);
            e2 += __shfl_xor_sync(0xffffffffu, e2, off);
        }
        r0 = 1.0f / e0; r1 = 1.0f / e1; r2 = 1.0f / e2;
#pragma unroll
        for (int q = 0; q < 4; ++q) {
            int a = lane + 32 * q;
            if (a < cnt) {
                swp[a * 3 + 0] = sc[q][0] * r0;
                swp[a * 3 + 1] = sc[q][1] * r1;
                swp[a * 3 + 2] = sc[q][2] * r2;
            }
        }
        __syncwarp();

#pragma unroll 4
        for (int a = 0; a < cnt; ++a) {
            float2 xv = X2[(size_t)(s0 + a) * (D_DIM / 2) + lane];
            ull xx = *reinterpret_cast<ull*>(&xv);
            acc0 = fma2(xx, pack2(swp[a * 3 + 0]), acc0);
            acc1 = fma2(xx, pack2(swp[a * 3 + 1]), acc1);
            acc2 = fma2(xx, pack2(swp[a * 3 + 2]), acc2);
        }
    } else {
        for (int n = s0 + lane; n < s1; n += 32) {
            size_t o = (size_t)n * H_DIM;
            m0 = fmaxf(m0, g_scores[o + 0]);
            m1 = fmaxf(m1, g_scores[o + 1]);
            m2 = fmaxf(m2, g_scores[o + 2]);
        }
#pragma unroll
        for (int off = 16; off; off >>= 1) {
            m0 = fmaxf(m0, __shfl_xor_sync(0xffffffffu, m0, off));
            m1 = fmaxf(m1, __shfl_xor_sync(0xffffffffu, m1, off));
            m2 = fmaxf(m2, __shfl_xor_sync(0xffffffffu, m2, off));
        }
        float e0 = 0.f, e1 = 0.f, e2 = 0.f;
        for (int n = s0 + lane; n < s1; n += 32) {
            size_t o = (size_t)n * H_DIM;
            e0 += __expf(g_scores[o + 0] - m0);
            e1 += __expf(g_scores[o + 1] - m1);
            e2 += __expf(g_scores[o + 2] - m2);
        }
#pragma unroll
        for (int off = 16; off; off >>= 1) {
            e0 += __shfl_xor_sync(0xffffffffu, e0, off);
            e1 += __shfl_xor_sync(0xffffffffu, e1, off);
            e2 += __shfl_xor_sync(0xffffffffu, e2, off);
        }
        r0 = 1.0f / e0; r1 = 1.0f / e1; r2 = 1.0f / e2;

        for (int base = 0; base < cnt; base += SEG_CAP) {
            int c = min(SEG_CAP, cnt - base);
#pragma unroll
            for (int q = 0; q < 4; ++q) {
                int a = lane + 32 * q;
                if (a < c) {
                    size_t o = (size_t)(s0 + base + a) * H_DIM;
                    swp[a * 3 + 0] = __expf(g_scores[o + 0] - m0) * r0;
                    swp[a * 3 + 1] = __expf(g_scores[o + 1] - m1) * r1;
                    swp[a * 3 + 2] = __expf(g_scores[o + 2] - m2) * r2;
                }
            }
            __syncwarp();
#pragma unroll 4
            for (int a = 0; a < c; ++a) {
                float2 xv = X2[(size_t)(s0 + base + a) * (D_DIM / 2) + lane];
                ull xx = *reinterpret_cast<ull*>(&xv);
                acc0 = fma2(xx, pack2(swp[a * 3 + 0]), acc0);
                acc1 = fma2(xx, pack2(swp[a * 3 + 1]), acc1);
                acc2 = fma2(xx, pack2(swp[a * 3 + 2]), acc2);
            }
            __syncwarp();
        }
    }

    float v00, v01, v10, v11, v20, v21;
    unpack2(acc0, v00, v01);
    unpack2(acc1, v10, v11);
    unpack2(acc2, v20, v21);
    float* po = outg + lane * 6;
    po[0] = v00; po[1] = v10; po[2] = v20;
    po[3] = v01; po[4] = v11; po[5] = v21;
}

// ---------------------------------------------------------------------------
extern "C" void kernel_launch(void* const* d_in, const int* in_sizes, int n_in,
                              void* d_out, int out_size)
{
    const float* X     = (const float*)d_in[0];
    const float* w1    = (const float*)d_in[1];
    const float* b1    = (const float*)d_in[2];
    const float* w2    = (const float*)d_in[3];
    const float* b2    = (const float*)d_in[4];
    const int*   owner = (const int*)  d_in[5];

    const int N = in_sizes[5];
    const int G = out_size / (D_DIM * H_DIM);

    k_scores<<<(N + 511) / 512, 256>>>(X, w1, b1, w2, b2, N);
    k_bounds<<<(N + 255) / 256, 256>>>(owner, N, G);
    k_pool<<<(G + 3) / 4, 128>>>(X, (float*)d_out, G);
}

// round 5
// speedup vs baseline: 2.6926x; 1.7476x over previous
#include <cuda_runtime.h>
#include <cuda_bf16.h>
#include <cstdint>

// Problem shape (fixed by dataset): N=2,000,000 atoms, D=64, HID=32, H=3, G=50,000
#define D_DIM   64
#define HID_DIM 32
#define H_DIM   3

#define MAX_N 2000000
#define MAX_G 50000
#define SEG_CAP 128

typedef unsigned long long ull;

// Scratch (device globals: no allocation allowed in kernel_launch)
__device__ float g_scores[(size_t)MAX_N * H_DIM];   // 24 MB
__device__ int   g_segstart[MAX_G + 1];

// ---------------- packed fp32x2 helpers ----------------
__device__ __forceinline__ ull pack2(float v) {
    ull r; asm("mov.b64 %0, {%1, %1};" : "=l"(r) : "f"(v)); return r;
}
__device__ __forceinline__ ull fma2(ull a, ull b, ull c) {
    ull d; asm("fma.rn.f32x2 %0, %1, %2, %3;" : "=l"(d) : "l"(a), "l"(b), "l"(c)); return d;
}
__device__ __forceinline__ void unpack2(ull v, float& lo, float& hi) {
    asm("mov.b64 {%0, %1}, %2;" : "=f"(lo), "=f"(hi) : "l"(v));
}

// ---------------- bf16 helpers ----------------
__device__ __forceinline__ uint32_t pk2bf(float a, float b) {
    __nv_bfloat162 h = __floats2bfloat162_rn(a, b);   // .x=a (low), .y=b (high)
    return *reinterpret_cast<uint32_t*>(&h);
}
__device__ __forceinline__ float bfhi(float x) {
    return __bfloat162float(__float2bfloat16_rn(x));
}

// warp-level tensor-core MMA (sm_80+ feature set; compiles for plain sm_103)
__device__ __forceinline__ void mma16816(float c[4],
    uint32_t a0, uint32_t a1, uint32_t a2, uint32_t a3,
    uint32_t b0, uint32_t b1)
{
    asm volatile(
        "mma.sync.aligned.m16n8k16.row.col.f32.bf16.bf16.f32 "
        "{%0,%1,%2,%3}, {%4,%5,%6,%7}, {%8,%9}, {%0,%1,%2,%3};"
        : "+f"(c[0]), "+f"(c[1]), "+f"(c[2]), "+f"(c[3])
        : "r"(a0), "r"(a1), "r"(a2), "r"(a3), "r"(b0), "r"(b1));
}

// ---------------------------------------------------------------------------
// Kernel 1 (tensor-core, mma.sync): per-atom MLP scores.
// Persistent warps; each warp-tile = 16 atoms. Double-bf16 3-term split:
//   X@W ~= Xhi@Whi + Xhi@Wlo + Xlo@Whi   (error ~2^-18 per product)
// A fragments loaded straight from gmem; B (w1) fragments live in registers.
// ---------------------------------------------------------------------------
__global__ __launch_bounds__(128) void k_scores_mma(
    const float* __restrict__ X,
    const float* __restrict__ w1, const float* __restrict__ b1,
    const float* __restrict__ w2, const float* __restrict__ b2,
    int N, int ntiles)
{
    const int lane = threadIdx.x & 31;
    const int wid  = threadIdx.x >> 5;
    const int g    = lane >> 2;   // row group 0..7
    const int tig  = lane & 3;    // thread-in-group

    // ---- B fragments (w1, hi/lo) in registers: b[t][s][2] ----
    uint32_t bh[4][4][2], bl[4][4][2];
#pragma unroll
    for (int t = 0; t < 4; ++t) {
        const int col = g + 8 * t;          // hid col 0..31
#pragma unroll
        for (int s = 0; s < 4; ++s) {
            const int k0 = tig * 2 + 16 * s;
            float w00 = __ldg(&w1[(k0 + 0) * HID_DIM + col]);
            float w01 = __ldg(&w1[(k0 + 1) * HID_DIM + col]);
            float w08 = __ldg(&w1[(k0 + 8) * HID_DIM + col]);
            float w09 = __ldg(&w1[(k0 + 9) * HID_DIM + col]);
            bh[t][s][0] = pk2bf(w00, w01);
            bh[t][s][1] = pk2bf(w08, w09);
            bl[t][s][0] = pk2bf(w00 - bfhi(w00), w01 - bfhi(w01));
            bl[t][s][1] = pk2bf(w08 - bfhi(w08), w09 - bfhi(w09));
        }
    }

    // ---- epilogue constants for this thread's 8 hid columns ----
    float b1v[4][2], w2v[4][2][3];
#pragma unroll
    for (int t = 0; t < 4; ++t)
#pragma unroll
        for (int e = 0; e < 2; ++e) {
            const int col = 8 * t + tig * 2 + e;
            b1v[t][e] = __ldg(&b1[col]);
            w2v[t][e][0] = __ldg(&w2[col * H_DIM + 0]);
            w2v[t][e][1] = __ldg(&w2[col * H_DIM + 1]);
            w2v[t][e][2] = __ldg(&w2[col * H_DIM + 2]);
        }
    const float bb0 = __ldg(&b2[0]), bb1 = __ldg(&b2[1]), bb2 = __ldg(&b2[2]);

    const int warp0 = blockIdx.x * 4 + wid;
    const int nwarp = gridDim.x * 4;

    for (int tile = warp0; tile < ntiles; tile += nwarp) {
        float acc[4][4];
#pragma unroll
        for (int t = 0; t < 4; ++t) {
            acc[t][0] = 0.f; acc[t][1] = 0.f; acc[t][2] = 0.f; acc[t][3] = 0.f;
        }

        const int r0 = tile * 16 + g;
        const int r1 = r0 + 8;
        const float* x0 = X + (size_t)(r0 < N ? r0 : N - 1) * D_DIM;
        const float* x1 = X + (size_t)(r1 < N ? r1 : N - 1) * D_DIM;

#pragma unroll
        for (int s = 0; s < 4; ++s) {
            const int ks = 16 * s + tig * 2;
            float2 v0 = *reinterpret_cast<const float2*>(x0 + ks);
            float2 v1 = *reinterpret_cast<const float2*>(x1 + ks);
            float2 v2 = *reinterpret_cast<const float2*>(x0 + ks + 8);
            float2 v3 = *reinterpret_cast<const float2*>(x1 + ks + 8);

            uint32_t ah0 = pk2bf(v0.x, v0.y);
            uint32_t ah1 = pk2bf(v1.x, v1.y);
            uint32_t ah2 = pk2bf(v2.x, v2.y);
            uint32_t ah3 = pk2bf(v3.x, v3.y);
            uint32_t al0 = pk2bf(v0.x - bfhi(v0.x), v0.y - bfhi(v0.y));
            uint32_t al1 = pk2bf(v1.x - bfhi(v1.x), v1.y - bfhi(v1.y));
            uint32_t al2 = pk2bf(v2.x - bfhi(v2.x), v2.y - bfhi(v2.y));
            uint32_t al3 = pk2bf(v3.x - bfhi(v3.x), v3.y - bfhi(v3.y));

#pragma unroll
            for (int t = 0; t < 4; ++t) {
                mma16816(acc[t], ah0, ah1, ah2, ah3, bh[t][s][0], bh[t][s][1]);
                mma16816(acc[t], ah0, ah1, ah2, ah3, bl[t][s][0], bl[t][s][1]);
                mma16816(acc[t], al0, al1, al2, al3, bh[t][s][0], bh[t][s][1]);
            }
        }

        // ---- epilogue: +b1, SiLU, @w2, reduce over the 4-lane group ----
#pragma unroll
        for (int row = 0; row < 2; ++row) {
            float q0 = 0.f, q1 = 0.f, q2 = 0.f;
#pragma unroll
            for (int t = 0; t < 4; ++t)
#pragma unroll
                for (int e = 0; e < 2; ++e) {
                    float h = acc[t][row * 2 + e] + b1v[t][e];
                    float act = __fdividef(h, 1.0f + __expf(-h));
                    q0 = fmaf(act, w2v[t][e][0], q0);
                    q1 = fmaf(act, w2v[t][e][1], q1);
                    q2 = fmaf(act, w2v[t][e][2], q2);
                }
            q0 += __shfl_xor_sync(0xffffffffu, q0, 1);
            q0 += __shfl_xor_sync(0xffffffffu, q0, 2);
            q1 += __shfl_xor_sync(0xffffffffu, q1, 1);
            q1 += __shfl_xor_sync(0xffffffffu, q1, 2);
            q2 += __shfl_xor_sync(0xffffffffu, q2, 1);
            q2 += __shfl_xor_sync(0xffffffffu, q2, 2);

            const int atom = tile * 16 + g + 8 * row;
            if (tig == 0 && atom < N) {
                size_t o = (size_t)atom * H_DIM;
                g_scores[o + 0] = q0 + bb0;
                g_scores[o + 1] = q1 + bb1;
                g_scores[o + 2] = q2 + bb2;
            }
        }
    }
}

// ---------------------------------------------------------------------------
// Kernel 2: segment boundaries from sorted owner array.
// ---------------------------------------------------------------------------
__global__ void k_bounds(const int* __restrict__ owner, int N, int G)
{
    int i = blockIdx.x * blockDim.x + threadIdx.x;
    if (i >= N) return;
    int o = owner[i];
    if (i == 0) {
        for (int g = 0; g <= o; ++g) g_segstart[g] = 0;
    } else {
        int po = owner[i - 1];
        for (int g = po + 1; g <= o; ++g) g_segstart[g] = i;
    }
    if (i == N - 1) {
        for (int g = o + 1; g <= G; ++g) g_segstart[g] = N;
    }
}

// ---------------------------------------------------------------------------
// Kernel 3: one WARP per segment (unchanged — performs at prediction).
// ---------------------------------------------------------------------------
__global__ __launch_bounds__(128) void k_pool(
    const float* __restrict__ X, float* __restrict__ out, int G)
{
    __shared__ float sw[4][SEG_CAP * H_DIM];

    const int warp = threadIdx.x >> 5;
    const int lane = threadIdx.x & 31;
    const int g    = blockIdx.x * 4 + warp;
    if (g >= G) return;

    const int s0  = g_segstart[g];
    const int s1  = g_segstart[g + 1];
    const int cnt = s1 - s0;

    float* outg = out + (size_t)g * (D_DIM * H_DIM);
    if (cnt <= 0) {
        for (int i = lane; i < D_DIM * H_DIM; i += 32) outg[i] = 0.f;
        return;
    }

    float* swp = sw[warp];
    const float2* X2 = reinterpret_cast<const float2*>(X);

    float m0 = -3.4e38f, m1 = -3.4e38f, m2 = -3.4e38f;
    float r0, r1, r2;
    ull acc0 = 0ull, acc1 = 0ull, acc2 = 0ull;

    if (cnt <= SEG_CAP) {
        float sc[4][3];
#pragma unroll
        for (int q = 0; q < 4; ++q) {
            int a = lane + 32 * q;
            if (a < cnt) {
                size_t o = (size_t)(s0 + a) * H_DIM;
                sc[q][0] = g_scores[o + 0];
                sc[q][1] = g_scores[o + 1];
                sc[q][2] = g_scores[o + 2];
                m0 = fmaxf(m0, sc[q][0]);
                m1 = fmaxf(m1, sc[q][1]);
                m2 = fmaxf(m2, sc[q][2]);
            }
        }
#pragma unroll
        for (int off = 16; off; off >>= 1) {
            m0 = fmaxf(m0, __shfl_xor_sync(0xffffffffu, m0, off));
            m1 = fmaxf(m1, __shfl_xor_sync(0xffffffffu, m1, off));
            m2 = fmaxf(m2, __shfl_xor_sync(0xffffffffu, m2, off));
        }
        float e0 = 0.f, e1 = 0.f, e2 = 0.f;
#pragma unroll
        for (int q = 0; q < 4; ++q) {
            int a = lane + 32 * q;
            if (a < cnt) {
                sc[q][0] = __expf(sc[q][0] - m0); e0 += sc[q][0];
                sc[q][1] = __expf(sc[q][1] - m1); e1 += sc[q][1];
                sc[q][2] = __expf(sc[q][2] - m2); e2 += sc[q][2];
            }
        }
#pragma unroll
        for (int off = 16; off; off >>= 1) {
            e0 += __shfl_xor_sync(0xffffffffu, e0, off);
            e1 += __shfl_xor_sync(0xffffffffu, e1, off);
            e2 += __shfl_xor_sync(0xffffffffu, e2, off);
        }
        r0 = 1.0f / e0; r1 = 1.0f / e1; r2 = 1.0f / e2;
#pragma unroll
        for (int q = 0; q < 4; ++q) {
            int a = lane + 32 * q;
            if (a < cnt) {
                swp[a * 3 + 0] = sc[q][0] * r0;
                swp[a * 3 + 1] = sc[q][1] * r1;
                swp[a * 3 + 2] = sc[q][2] * r2;
            }
        }
        __syncwarp();

#pragma unroll 4
        for (int a = 0; a < cnt; ++a) {
            float2 xv = X2[(size_t)(s0 + a) * (D_DIM / 2) + lane];
            ull xx = *reinterpret_cast<ull*>(&xv);
            acc0 = fma2(xx, pack2(swp[a * 3 + 0]), acc0);
            acc1 = fma2(xx, pack2(swp[a * 3 + 1]), acc1);
            acc2 = fma2(xx, pack2(swp[a * 3 + 2]), acc2);
        }
    } else {
        for (int n = s0 + lane; n < s1; n += 32) {
            size_t o = (size_t)n * H_DIM;
            m0 = fmaxf(m0, g_scores[o + 0]);
            m1 = fmaxf(m1, g_scores[o + 1]);
            m2 = fmaxf(m2, g_scores[o + 2]);
        }
#pragma unroll
        for (int off = 16; off; off >>= 1) {
            m0 = fmaxf(m0, __shfl_xor_sync(0xffffffffu, m0, off));
            m1 = fmaxf(m1, __shfl_xor_sync(0xffffffffu, m1, off));
            m2 = fmaxf(m2, __shfl_xor_sync(0xffffffffu, m2, off));
        }
        float e0 = 0.f, e1 = 0.f, e2 = 0.f;
        for (int n = s0 + lane; n < s1; n += 32) {
            size_t o = (size_t)n * H_DIM;
            e0 += __expf(g_scores[o + 0] - m0);
            e1 += __expf(g_scores[o + 1] - m1);
            e2 += __expf(g_scores[o + 2] - m2);
        }
#pragma unroll
        for (int off = 16; off; off >>= 1) {
            e0 += __shfl_xor_sync(0xffffffffu, e0, off);
            e1 += __shfl_xor_sync(0xffffffffu, e1, off);
            e2 += __shfl_xor_sync(0xffffffffu, e2, off);
        }
        r0 = 1.0f / e0; r1 = 1.0f / e1; r2 = 1.0f / e2;

        for (int base = 0; base < cnt; base += SEG_CAP) {
            int c = min(SEG_CAP, cnt - base);
#pragma unroll
            for (int q = 0; q < 4; ++q) {
                int a = lane + 32 * q;
                if (a < c) {
                    size_t o = (size_t)(s0 + base + a) * H_DIM;
                    swp[a * 3 + 0] = __expf(g_scores[o + 0] - m0) * r0;
                    swp[a * 3 + 1] = __expf(g_scores[o + 1] - m1) * r1;
                    swp[a * 3 + 2] = __expf(g_scores[o + 2] - m2) * r2;
                }
            }
            __syncwarp();
#pragma unroll 4
            for (int a = 0; a < c; ++a) {
                float2 xv = X2[(size_t)(s0 + base + a) * (D_DIM / 2) + lane];
                ull xx = *reinterpret_cast<ull*>(&xv);
                acc0 = fma2(xx, pack2(swp[a * 3 + 0]), acc0);
                acc1 = fma2(xx, pack2(swp[a * 3 + 1]), acc1);
                acc2 = fma2(xx, pack2(swp[a * 3 + 2]), acc2);
            }
            __syncwarp();
        }
    }

    float v00, v01, v10, v11, v20, v21;
    unpack2(acc0, v00, v01);
    unpack2(acc1, v10, v11);
    unpack2(acc2, v20, v21);
    float* po = outg + lane * 6;
    po[0] = v00; po[1] = v10; po[2] = v20;
    po[3] = v01; po[4] = v11; po[5] = v21;
}

// ---------------------------------------------------------------------------
extern "C" void kernel_launch(void* const* d_in, const int* in_sizes, int n_in,
                              void* d_out, int out_size)
{
    const float* X     = (const float*)d_in[0];
    const float* w1    = (const float*)d_in[1];
    const float* b1    = (const float*)d_in[2];
    const float* w2    = (const float*)d_in[3];
    const float* b2    = (const float*)d_in[4];
    const int*   owner = (const int*)  d_in[5];

    const int N = in_sizes[5];
    const int G = out_size / (D_DIM * H_DIM);
    const int ntiles = (N + 15) / 16;

    k_scores_mma<<<444, 128>>>(X, w1, b1, w2, b2, N, ntiles);
    k_bounds<<<(N + 255) / 256, 256>>>(owner, N, G);
    k_pool<<<(G + 3) / 4, 128>>>(X, (float*)d_out, G);
}